// round 8
// baseline (speedup 1.0000x reference)
#include <cuda_runtime.h>

#define N_NODES 100000
#define N_EDGES 1600000

// Scratch (__device__ globals; zero-initialized at load; k_final re-zeroes
// g_deg/g_agg so the invariant holds for every call -> deterministic)
__device__ float  g_deg[N_NODES];
__device__ float  g_dis[N_NODES];
__device__ float2 g_y[N_NODES];        // y[n] = dis[n] * x[n]
__device__ float2 g_agg[N_NODES];      // layer-1 raw scatter target
__device__ float  g_t[N_NODES];        // t[n] = dis[n] * s[n]

// v2 float reduction (one L2 sector instead of two)
__device__ __forceinline__ void red_add_v2(float2* addr, float a, float b) {
    asm volatile("red.global.add.v2.f32 [%0], {%1, %2};"
                 :: "l"(addr), "f"(a), "f"(b) : "memory");
}

// ---------------------------------------------------------------------------
// K1: degree of target nodes (4 edges/thread, int4 stream)
__global__ void __launch_bounds__(256) k_deg(const int4* __restrict__ col4) {
    int i = blockIdx.x * blockDim.x + threadIdx.x;
    if (i < N_EDGES / 4) {
        int4 c = col4[i];
        atomicAdd(&g_deg[c.x], 1.0f);
        atomicAdd(&g_deg[c.y], 1.0f);
        atomicAdd(&g_deg[c.z], 1.0f);
        atomicAdd(&g_deg[c.w], 1.0f);
    }
}

// K2: dis = deg^-1/2 (0 if deg==0);  y[n] = dis[n]*x[n];  zero out[]
__global__ void __launch_bounds__(256) k_dis(const float* __restrict__ x,
                                             float* __restrict__ out) {
    int n = blockIdx.x * blockDim.x + threadIdx.x;
    if (n < N_NODES) {
        float d   = g_deg[n];
        float dis = (d > 0.0f) ? rsqrtf(d) : 0.0f;
        g_dis[n]  = dis;
        float2 xv = ((const float2*)x)[n];
        g_y[n]    = make_float2(dis * xv.x, dis * xv.y);
        out[n]    = 0.0f;
    }
}

// K3: layer-1 edge scatter: agg_raw[c] += y[r]  (4 edges/thread, batched gathers)
__global__ void __launch_bounds__(256) k_edge1(const int4* __restrict__ row4,
                                               const int4* __restrict__ col4) {
    int i = blockIdx.x * blockDim.x + threadIdx.x;
    if (i < N_EDGES / 4) {
        int4 r = row4[i];
        int4 c = col4[i];
        float2 y0 = g_y[r.x];
        float2 y1 = g_y[r.y];
        float2 y2 = g_y[r.z];
        float2 y3 = g_y[r.w];
        red_add_v2(&g_agg[c.x], y0.x, y0.y);
        red_add_v2(&g_agg[c.y], y1.x, y1.y);
        red_add_v2(&g_agg[c.z], y2.x, y2.y);
        red_add_v2(&g_agg[c.w], y3.x, y3.y);
    }
}

// K4: per-node MLP middle — 2 threads per node (32 features each),
//     float4-packed weights (1 LDS.128 per feature), shfl-pair combine.
//   s[n] = sum_f relu(a0*W1a[f] + a1*W1b[f] + b1[f]) * W2[f];  t[n] = dis*s
__global__ void __launch_bounds__(256) k_nodemid(const float* __restrict__ W1,
                                                 const float* __restrict__ b1,
                                                 const float* __restrict__ W2) {
    __shared__ float4 s_w[64];   // (W1a, W1b, b1, W2) per feature
    int t = threadIdx.x;
    if (t < 64) {
        s_w[t] = make_float4(W1[t], W1[64 + t], b1[t], W2[t]);
    }
    __syncthreads();
    int g    = blockIdx.x * blockDim.x + t;
    int n    = g >> 1;           // node
    int half = g & 1;            // feature half: [0,32) or [32,64)
    if (n < N_NODES) {
        float dis = g_dis[n];
        float2 ar = g_agg[n];
        float a0 = dis * ar.x;
        float a1 = dis * ar.y;
        int base = half << 5;
        float s0 = 0.0f, s1 = 0.0f, s2 = 0.0f, s3 = 0.0f;
#pragma unroll
        for (int f = 0; f < 32; f += 4) {
            float4 w0 = s_w[base + f + 0];
            float4 w1 = s_w[base + f + 1];
            float4 w2 = s_w[base + f + 2];
            float4 w3 = s_w[base + f + 3];
            float h0 = fmaf(a1, w0.y, fmaf(a0, w0.x, w0.z));
            float h1 = fmaf(a1, w1.y, fmaf(a0, w1.x, w1.z));
            float h2 = fmaf(a1, w2.y, fmaf(a0, w2.x, w2.z));
            float h3 = fmaf(a1, w3.y, fmaf(a0, w3.x, w3.z));
            s0 = fmaf(fmaxf(h0, 0.0f), w0.w, s0);
            s1 = fmaf(fmaxf(h1, 0.0f), w1.w, s1);
            s2 = fmaf(fmaxf(h2, 0.0f), w2.w, s2);
            s3 = fmaf(fmaxf(h3, 0.0f), w3.w, s3);
        }
        float s = (s0 + s1) + (s2 + s3);
        // partner lane (lane^1) holds the other 32 features of the same node
        s += __shfl_xor_sync(0xffffffffu, s, 1);
        if (half == 0) {
            g_t[n] = dis * s;
        }
    }
}

// K5: layer-2 edge scatter: out_raw[c] += t[r]  (4 edges/thread)
__global__ void __launch_bounds__(256) k_edge2(const int4* __restrict__ row4,
                                               const int4* __restrict__ col4,
                                               float* __restrict__ out) {
    int i = blockIdx.x * blockDim.x + threadIdx.x;
    if (i < N_EDGES / 4) {
        int4 r = row4[i];
        int4 c = col4[i];
        float t0 = g_t[r.x];
        float t1 = g_t[r.y];
        float t2 = g_t[r.z];
        float t3 = g_t[r.w];
        atomicAdd(&out[c.x], t0);
        atomicAdd(&out[c.y], t1);
        atomicAdd(&out[c.z], t2);
        atomicAdd(&out[c.w], t3);
    }
}

// K6: out = relu(dis[n]*out_raw + b2); re-zero deg/agg for next call
__global__ void __launch_bounds__(256) k_final(float* __restrict__ out,
                                               const float* __restrict__ b2) {
    int n = blockIdx.x * blockDim.x + threadIdx.x;
    if (n < N_NODES) {
        out[n] = fmaxf(fmaf(g_dis[n], out[n], b2[0]), 0.0f);
        g_deg[n] = 0.0f;
        g_agg[n] = make_float2(0.0f, 0.0f);
    }
}

// ---------------------------------------------------------------------------
extern "C" void kernel_launch(void* const* d_in, const int* in_sizes, int n_in,
                              void* d_out, int out_size) {
    const float* x  = (const float*)d_in[0];   // [N,2] f32
    const int*   ei = (const int*)d_in[1];     // [2,E] int32 (JAX x64 off)
    const float* W1 = (const float*)d_in[2];   // [2,64]
    const float* b1 = (const float*)d_in[3];   // [64]
    const float* W2 = (const float*)d_in[4];   // [64,1]
    const float* b2 = (const float*)d_in[5];   // [1]
    float*       out = (float*)d_out;          // [N,1]

    const int4* row4 = (const int4*)ei;               // source
    const int4* col4 = (const int4*)(ei + N_EDGES);   // target

    const int BT = 256;
    const int nodeBlocks  = (N_NODES + BT - 1) / BT;
    const int pairBlocks  = (2 * N_NODES + BT - 1) / BT;
    const int edgeBlocks4 = (N_EDGES / 4 + BT - 1) / BT;

    k_deg    <<<edgeBlocks4, BT>>>(col4);
    k_dis    <<<nodeBlocks, BT>>>(x, out);
    k_edge1  <<<edgeBlocks4, BT>>>(row4, col4);
    k_nodemid<<<pairBlocks, BT>>>(W1, b1, W2);
    k_edge2  <<<edgeBlocks4, BT>>>(row4, col4, out);
    k_final  <<<nodeBlocks, BT>>>(out, b2);
}

// round 9
// speedup vs baseline: 1.0530x; 1.0530x over previous
#include <cuda_runtime.h>

#define N_NODES 100000
#define N_EDGES 1600000

// Scratch (__device__ globals; zero-initialized at load; k_final re-zeroes
// g_deg/g_agg so the invariant holds for every call -> deterministic)
__device__ float  g_deg[N_NODES];
__device__ float  g_dis[N_NODES];
__device__ float2 g_y[N_NODES];        // y[n] = dis[n] * x[n]
__device__ float2 g_agg[N_NODES];      // layer-1 raw scatter target
__device__ float  g_t[N_NODES];        // t[n] = dis[n] * s[n]

// v2 float reduction (one L2 sector instead of two)
__device__ __forceinline__ void red_add_v2(float2* addr, float a, float b) {
    asm volatile("red.global.add.v2.f32 [%0], {%1, %2};"
                 :: "l"(addr), "f"(a), "f"(b) : "memory");
}

// ---------------------------------------------------------------------------
// K1: degree of target nodes (4 edges/thread, int4 stream)
__global__ void __launch_bounds__(256) k_deg(const int4* __restrict__ col4) {
    int i = blockIdx.x * blockDim.x + threadIdx.x;
    if (i < N_EDGES / 4) {
        int4 c = col4[i];
        atomicAdd(&g_deg[c.x], 1.0f);
        atomicAdd(&g_deg[c.y], 1.0f);
        atomicAdd(&g_deg[c.z], 1.0f);
        atomicAdd(&g_deg[c.w], 1.0f);
    }
}

// K2: dis = deg^-1/2 (0 if deg==0);  y[n] = dis[n]*x[n];  zero out[]
__global__ void __launch_bounds__(256) k_dis(const float* __restrict__ x,
                                             float* __restrict__ out) {
    int n = blockIdx.x * blockDim.x + threadIdx.x;
    if (n < N_NODES) {
        float d   = g_deg[n];
        float dis = (d > 0.0f) ? rsqrtf(d) : 0.0f;
        g_dis[n]  = dis;
        float2 xv = ((const float2*)x)[n];
        g_y[n]    = make_float2(dis * xv.x, dis * xv.y);
        out[n]    = 0.0f;
    }
}

// K3: layer-1 edge scatter: agg_raw[c] += y[r]  (4 edges/thread, batched gathers)
__global__ void __launch_bounds__(256) k_edge1(const int4* __restrict__ row4,
                                               const int4* __restrict__ col4) {
    int i = blockIdx.x * blockDim.x + threadIdx.x;
    if (i < N_EDGES / 4) {
        int4 r = row4[i];
        int4 c = col4[i];
        float2 y0 = g_y[r.x];
        float2 y1 = g_y[r.y];
        float2 y2 = g_y[r.z];
        float2 y3 = g_y[r.w];
        red_add_v2(&g_agg[c.x], y0.x, y0.y);
        red_add_v2(&g_agg[c.y], y1.x, y1.y);
        red_add_v2(&g_agg[c.z], y2.x, y2.y);
        red_add_v2(&g_agg[c.w], y3.x, y3.y);
    }
}

// K4: per-node MLP middle — 1 thread/node, float4-packed weights,
//     node-data prefetch overlapping the weight-load prologue,
//     4 independent accumulators.
//   s[n] = sum_f relu(a0*W1a[f] + a1*W1b[f] + b1[f]) * W2[f];  t[n] = dis*s
__global__ void __launch_bounds__(256) k_nodemid(const float* __restrict__ W1,
                                                 const float* __restrict__ b1,
                                                 const float* __restrict__ W2) {
    __shared__ float4 s_w[64];   // (W1a, W1b, b1, W2) per feature
    int t = threadIdx.x;
    int n = blockIdx.x * blockDim.x + t;

    // Prefetch this node's data FIRST: its ~250-cyc L2 latency overlaps the
    // weight loads + barrier below instead of serializing after them.
    float  dis = 0.0f;
    float2 ar  = make_float2(0.0f, 0.0f);
    if (n < N_NODES) {
        dis = g_dis[n];
        ar  = g_agg[n];
    }
    if (t < 64) {
        s_w[t] = make_float4(W1[t], W1[64 + t], b1[t], W2[t]);
    }
    __syncthreads();

    if (n < N_NODES) {
        float a0 = dis * ar.x;
        float a1 = dis * ar.y;
        float s0 = 0.0f, s1 = 0.0f, s2 = 0.0f, s3 = 0.0f;
#pragma unroll
        for (int f = 0; f < 64; f += 4) {
            float4 w0 = s_w[f + 0];
            float4 w1 = s_w[f + 1];
            float4 w2 = s_w[f + 2];
            float4 w3 = s_w[f + 3];
            float h0 = fmaf(a1, w0.y, fmaf(a0, w0.x, w0.z));
            float h1 = fmaf(a1, w1.y, fmaf(a0, w1.x, w1.z));
            float h2 = fmaf(a1, w2.y, fmaf(a0, w2.x, w2.z));
            float h3 = fmaf(a1, w3.y, fmaf(a0, w3.x, w3.z));
            s0 = fmaf(fmaxf(h0, 0.0f), w0.w, s0);
            s1 = fmaf(fmaxf(h1, 0.0f), w1.w, s1);
            s2 = fmaf(fmaxf(h2, 0.0f), w2.w, s2);
            s3 = fmaf(fmaxf(h3, 0.0f), w3.w, s3);
        }
        g_t[n] = dis * ((s0 + s1) + (s2 + s3));
    }
}

// K5: layer-2 edge scatter: out_raw[c] += t[r]  (4 edges/thread)
__global__ void __launch_bounds__(256) k_edge2(const int4* __restrict__ row4,
                                               const int4* __restrict__ col4,
                                               float* __restrict__ out) {
    int i = blockIdx.x * blockDim.x + threadIdx.x;
    if (i < N_EDGES / 4) {
        int4 r = row4[i];
        int4 c = col4[i];
        float t0 = g_t[r.x];
        float t1 = g_t[r.y];
        float t2 = g_t[r.z];
        float t3 = g_t[r.w];
        atomicAdd(&out[c.x], t0);
        atomicAdd(&out[c.y], t1);
        atomicAdd(&out[c.z], t2);
        atomicAdd(&out[c.w], t3);
    }
}

// K6: out = relu(dis[n]*out_raw + b2); re-zero deg/agg for next call
__global__ void __launch_bounds__(256) k_final(float* __restrict__ out,
                                               const float* __restrict__ b2) {
    int n = blockIdx.x * blockDim.x + threadIdx.x;
    if (n < N_NODES) {
        out[n] = fmaxf(fmaf(g_dis[n], out[n], b2[0]), 0.0f);
        g_deg[n] = 0.0f;
        g_agg[n] = make_float2(0.0f, 0.0f);
    }
}

// ---------------------------------------------------------------------------
extern "C" void kernel_launch(void* const* d_in, const int* in_sizes, int n_in,
                              void* d_out, int out_size) {
    const float* x  = (const float*)d_in[0];   // [N,2] f32
    const int*   ei = (const int*)d_in[1];     // [2,E] int32 (JAX x64 off)
    const float* W1 = (const float*)d_in[2];   // [2,64]
    const float* b1 = (const float*)d_in[3];   // [64]
    const float* W2 = (const float*)d_in[4];   // [64,1]
    const float* b2 = (const float*)d_in[5];   // [1]
    float*       out = (float*)d_out;          // [N,1]

    const int4* row4 = (const int4*)ei;               // source
    const int4* col4 = (const int4*)(ei + N_EDGES);   // target

    const int BT = 256;
    const int nodeBlocks  = (N_NODES + BT - 1) / BT;
    const int edgeBlocks4 = (N_EDGES / 4 + BT - 1) / BT;

    k_deg    <<<edgeBlocks4, BT>>>(col4);
    k_dis    <<<nodeBlocks, BT>>>(x, out);
    k_edge1  <<<edgeBlocks4, BT>>>(row4, col4);
    k_nodemid<<<nodeBlocks, BT>>>(W1, b1, W2);
    k_edge2  <<<edgeBlocks4, BT>>>(row4, col4, out);
    k_final  <<<nodeBlocks, BT>>>(out, b2);
}

// round 10
// speedup vs baseline: 1.0876x; 1.0329x over previous
#include <cuda_runtime.h>

#define N_NODES 100000
#define N_EDGES 1600000

// Scratch (__device__ globals; zero-initialized at load; k_final re-zeroes
// g_deg/g_agg so the invariant holds for every call -> deterministic)
__device__ float  g_deg[N_NODES];
__device__ float  g_dis[N_NODES];
__device__ float2 g_y[N_NODES];        // y[n] = dis[n] * x[n]
__device__ float2 g_agg[N_NODES];      // layer-1 raw scatter target
__device__ float  g_t[N_NODES];        // t[n] = dis[n] * s[n]

// v2 float reduction (one L2 sector instead of two)
__device__ __forceinline__ void red_add_v2(float2* addr, float a, float b) {
    asm volatile("red.global.add.v2.f32 [%0], {%1, %2};"
                 :: "l"(addr), "f"(a), "f"(b) : "memory");
}

// ---------------------------------------------------------------------------
// K1: degree of target nodes (4 edges/thread, int4 stream)
__global__ void __launch_bounds__(256) k_deg(const int4* __restrict__ col4) {
    int i = blockIdx.x * blockDim.x + threadIdx.x;
    if (i < N_EDGES / 4) {
        int4 c = col4[i];
        atomicAdd(&g_deg[c.x], 1.0f);
        atomicAdd(&g_deg[c.y], 1.0f);
        atomicAdd(&g_deg[c.z], 1.0f);
        atomicAdd(&g_deg[c.w], 1.0f);
    }
}

// K2: dis = deg^-1/2 (0 if deg==0);  y[n] = dis[n]*x[n];  zero out[]
__global__ void __launch_bounds__(256) k_dis(const float* __restrict__ x,
                                             float* __restrict__ out) {
    int n = blockIdx.x * blockDim.x + threadIdx.x;
    if (n < N_NODES) {
        float d   = g_deg[n];
        float dis = (d > 0.0f) ? rsqrtf(d) : 0.0f;
        g_dis[n]  = dis;
        float2 xv = ((const float2*)x)[n];
        g_y[n]    = make_float2(dis * xv.x, dis * xv.y);
        out[n]    = 0.0f;
    }
}

// K3: layer-1 edge scatter: agg_raw[c] += y[r]  (4 edges/thread, batched gathers)
__global__ void __launch_bounds__(256) k_edge1(const int4* __restrict__ row4,
                                               const int4* __restrict__ col4) {
    int i = blockIdx.x * blockDim.x + threadIdx.x;
    if (i < N_EDGES / 4) {
        int4 r = row4[i];
        int4 c = col4[i];
        float2 y0 = g_y[r.x];
        float2 y1 = g_y[r.y];
        float2 y2 = g_y[r.z];
        float2 y3 = g_y[r.w];
        red_add_v2(&g_agg[c.x], y0.x, y0.y);
        red_add_v2(&g_agg[c.y], y1.x, y1.y);
        red_add_v2(&g_agg[c.z], y2.x, y2.y);
        red_add_v2(&g_agg[c.w], y3.x, y3.y);
    }
}

// K4: per-node MLP middle — 2 adjacent nodes per thread:
//     * agg for both nodes = one coalesced LDG.128, dis = one LDG.64
//     * each shared-weight LDS.128 feeds 8 FMA-pipe ops (2 independent chains)
//     * coalesced float2 store of both results
//   s[n] = sum_f relu(a0*W1a[f] + a1*W1b[f] + b1[f]) * W2[f];  t[n] = dis*s
__global__ void __launch_bounds__(128) k_nodemid(const float* __restrict__ W1,
                                                 const float* __restrict__ b1,
                                                 const float* __restrict__ W2) {
    __shared__ float4 s_w[64];   // (W1a, W1b, b1, W2) per feature
    int t = threadIdx.x;
    int g = blockIdx.x * blockDim.x + t;   // pair index: nodes 2g, 2g+1
    int n0 = 2 * g;

    // Prefetch both nodes' data FIRST (overlaps the weight-load prologue).
    float2 dis2 = make_float2(0.0f, 0.0f);
    float4 ar2  = make_float4(0.0f, 0.0f, 0.0f, 0.0f);
    if (n0 < N_NODES) {
        dis2 = ((const float2*)g_dis)[g];     // dis[2g], dis[2g+1]
        ar2  = ((const float4*)g_agg)[g];     // agg[2g].xy, agg[2g+1].xy
    }
    if (t < 64) {
        s_w[t] = make_float4(W1[t], W1[64 + t], b1[t], W2[t]);
    }
    __syncthreads();

    if (n0 < N_NODES) {
        float a0 = dis2.x * ar2.x, a1 = dis2.x * ar2.y;   // node 2g
        float c0 = dis2.y * ar2.z, c1 = dis2.y * ar2.w;   // node 2g+1
        float sa0 = 0.0f, sa1 = 0.0f, sb0 = 0.0f, sb1 = 0.0f;
#pragma unroll
        for (int f = 0; f < 64; f += 2) {
            float4 w0 = s_w[f + 0];
            float4 w1 = s_w[f + 1];
            float ha0 = fmaf(a1, w0.y, fmaf(a0, w0.x, w0.z));
            float hb0 = fmaf(c1, w0.y, fmaf(c0, w0.x, w0.z));
            float ha1 = fmaf(a1, w1.y, fmaf(a0, w1.x, w1.z));
            float hb1 = fmaf(c1, w1.y, fmaf(c0, w1.x, w1.z));
            sa0 = fmaf(fmaxf(ha0, 0.0f), w0.w, sa0);
            sb0 = fmaf(fmaxf(hb0, 0.0f), w0.w, sb0);
            sa1 = fmaf(fmaxf(ha1, 0.0f), w1.w, sa1);
            sb1 = fmaf(fmaxf(hb1, 0.0f), w1.w, sb1);
        }
        float2 res = make_float2(dis2.x * (sa0 + sa1), dis2.y * (sb0 + sb1));
        ((float2*)g_t)[g] = res;
    }
}

// K5: layer-2 edge scatter: out_raw[c] += t[r]  (4 edges/thread)
__global__ void __launch_bounds__(256) k_edge2(const int4* __restrict__ row4,
                                               const int4* __restrict__ col4,
                                               float* __restrict__ out) {
    int i = blockIdx.x * blockDim.x + threadIdx.x;
    if (i < N_EDGES / 4) {
        int4 r = row4[i];
        int4 c = col4[i];
        float t0 = g_t[r.x];
        float t1 = g_t[r.y];
        float t2 = g_t[r.z];
        float t3 = g_t[r.w];
        atomicAdd(&out[c.x], t0);
        atomicAdd(&out[c.y], t1);
        atomicAdd(&out[c.z], t2);
        atomicAdd(&out[c.w], t3);
    }
}

// K6: out = relu(dis[n]*out_raw + b2); re-zero deg/agg for next call
__global__ void __launch_bounds__(256) k_final(float* __restrict__ out,
                                               const float* __restrict__ b2) {
    int n = blockIdx.x * blockDim.x + threadIdx.x;
    if (n < N_NODES) {
        out[n] = fmaxf(fmaf(g_dis[n], out[n], b2[0]), 0.0f);
        g_deg[n] = 0.0f;
        g_agg[n] = make_float2(0.0f, 0.0f);
    }
}

// ---------------------------------------------------------------------------
extern "C" void kernel_launch(void* const* d_in, const int* in_sizes, int n_in,
                              void* d_out, int out_size) {
    const float* x  = (const float*)d_in[0];   // [N,2] f32
    const int*   ei = (const int*)d_in[1];     // [2,E] int32 (JAX x64 off)
    const float* W1 = (const float*)d_in[2];   // [2,64]
    const float* b1 = (const float*)d_in[3];   // [64]
    const float* W2 = (const float*)d_in[4];   // [64,1]
    const float* b2 = (const float*)d_in[5];   // [1]
    float*       out = (float*)d_out;          // [N,1]

    const int4* row4 = (const int4*)ei;               // source
    const int4* col4 = (const int4*)(ei + N_EDGES);   // target

    const int BT = 256;
    const int nodeBlocks  = (N_NODES + BT - 1) / BT;
    const int edgeBlocks4 = (N_EDGES / 4 + BT - 1) / BT;
    const int pairBlocks  = (N_NODES / 2 + 127) / 128;   // 2 nodes/thread, BT=128

    k_deg    <<<edgeBlocks4, BT>>>(col4);
    k_dis    <<<nodeBlocks, BT>>>(x, out);
    k_edge1  <<<edgeBlocks4, BT>>>(row4, col4);
    k_nodemid<<<pairBlocks, 128>>>(W1, b1, W2);
    k_edge2  <<<edgeBlocks4, BT>>>(row4, col4, out);
    k_final  <<<nodeBlocks, BT>>>(out, b2);
}